// round 8
// baseline (speedup 1.0000x reference)
#include <cuda_runtime.h>

#define MM 8192
#define KMAX 14
#define NROWCHUNK 64
#define ROWS_PER_CHUNK (MM / NROWCHUNK)   // 128
#define NCOLTILE 8
#define COLS_PER_TILE (MM / NCOLTILE)     // 1024 (128 threads x 8 floats)
#define KEEP_CHUNKS 22                    // 22*128 rows * 32KB/row = 88 MB pinned in L2

#define DMF   ((float)(0.9 / 8192.0))               // DELTA_M as f32
#define CGAM  ((float)(1.0 / (1.0 - 0.45 + 1e-12))) // 1/(M_MAX-M_MIN+EPS) as f32
#define COEF2DM ((float)(2.0 * 0.9 / 8192.0))       // 2*DELTA_M as f32

// ---------------- device state (no allocations allowed) ----------------
__device__ __align__(16) float d_n[MM];
__device__ __align__(16) float d_ntmp[MM];
__device__ __align__(16) float d_v[MM];
__device__ __align__(16) float d_G[MM];
__device__ __align__(16) float4 d_part4[NROWCHUNK * MM / 4];  // 2 MB
__device__ float d_S;      // S_hat
__device__ int   d_N;
__device__ float d_h, d_h2, d_h6;

// ---------------- 256-bit L2 eviction-hinted loads (sm_103a requires .v4.b64) ----
struct f8 { float v[8]; };

__device__ __forceinline__ f8 ld_keep(const void* p) {
    unsigned long long x0, x1, x2, x3;
    asm("ld.global.nc.L2::evict_last.v4.b64 {%0,%1,%2,%3}, [%4];"
        : "=l"(x0), "=l"(x1), "=l"(x2), "=l"(x3) : "l"(p));
    f8 r;
    r.v[0] = __uint_as_float((unsigned)x0); r.v[1] = __uint_as_float((unsigned)(x0 >> 32));
    r.v[2] = __uint_as_float((unsigned)x1); r.v[3] = __uint_as_float((unsigned)(x1 >> 32));
    r.v[4] = __uint_as_float((unsigned)x2); r.v[5] = __uint_as_float((unsigned)(x2 >> 32));
    r.v[6] = __uint_as_float((unsigned)x3); r.v[7] = __uint_as_float((unsigned)(x3 >> 32));
    return r;
}
__device__ __forceinline__ f8 ld_stream(const void* p) {
    unsigned long long x0, x1, x2, x3;
    asm("ld.global.nc.L2::evict_first.v4.b64 {%0,%1,%2,%3}, [%4];"
        : "=l"(x0), "=l"(x1), "=l"(x2), "=l"(x3) : "l"(p));
    f8 r;
    r.v[0] = __uint_as_float((unsigned)x0); r.v[1] = __uint_as_float((unsigned)(x0 >> 32));
    r.v[2] = __uint_as_float((unsigned)x1); r.v[3] = __uint_as_float((unsigned)(x1 >> 32));
    r.v[4] = __uint_as_float((unsigned)x2); r.v[5] = __uint_as_float((unsigned)(x2 >> 32));
    r.v[6] = __uint_as_float((unsigned)x3); r.v[7] = __uint_as_float((unsigned)(x3 >> 32));
    return r;
}

// ---------------- init: copy state; compute N,h exactly like _num_substeps (f64) ----
__global__ void k_init(const float* __restrict__ x, const float* __restrict__ m) {
    const int t = threadIdx.x;
    for (int i = t; i < MM; i += 256) d_n[i] = x[i];

    __shared__ double sred[256];
    const double S_hat = (double)x[MM];
    const double S     = 10.0 * S_hat;
    const double alpha = 0.8 * S / (2.0 + S + 1e-12);
    const double csub  = 1.0 / (1.0 - 0.45 + 1e-12);

    double lmax = 0.0;
    for (int i = t; i < MM; i += 256) {
        double md = (double)m[i];
        double g  = 1.0 / (1.0 - md + 1e-12) - csub;
        if (g < 0.0) g = 0.0;
        double G = g * (alpha * md);
        if (G > lmax) lmax = G;
    }
    sred[t] = lmax;
    __syncthreads();
    for (int s = 128; s > 0; s >>= 1) {
        if (t < s) sred[t] = fmax(sred[t], sred[t + s]);
        __syncthreads();
    }
    if (t == 0) {
        d_S = x[MM];
        const double vmax = fabs(alpha) * (double)m[MM - 1];
        const double dm   = 0.9 / 8192.0;
        const double cfl  = vmax * 0.002 / (dm + 1e-12);
        int Ncfl = (vmax == 0.0 || cfl <= 0.8) ? 1 : (int)ceil(cfl / 0.8);
        const double rr = sred[0] * 0.002;
        int Nre = (sred[0] == 0.0 || rr <= 0.5) ? 1 : (int)ceil(rr / 0.5);
        int N = Ncfl > Nre ? Ncfl : Nre;
        if (N < 1) N = 1;
        if (N > KMAX) N = KMAX;   // provably never triggers (N<=14)
        d_N = N;
        double h = 0.002 / (double)N;
        d_h  = (float)h;
        d_h2 = (float)(0.5 * h);
        d_h6 = (float)(h / 6.0);
    }
}

// ---------------- per-substep: RK4 transport + G/v/uptake/S update (1 block) ----------
__global__ __launch_bounds__(1024, 1)
void k_transport(const float* __restrict__ m, int step) {
    if (step >= d_N) return;

    __shared__ float sa[MM];       // RK4 stage input
    __shared__ float sred[1024];   // uptake reduction

    const int t    = threadIdx.x;
    const int base = t * 8;
    const float invDM = 1.0f / DMF;

    const float Sh = d_S;                     // S_hat
    const float S  = 10.0f * Sh;              // S = S_MAX * S_hat
    const float h  = d_h;
    const float h2 = d_h2;
    const float h6 = d_h6;
    const float alphaT = 0.8f * S / (2.0f + S);            // transport alpha (no EPS)
    const float alphaE = 0.8f * S / (2.0f + S + 1e-12f);   // _r_g alpha (with EPS)

    float rn[8], rm[8], racc[8], rk[8];
    float rmL = (base > 0) ? m[base - 1] : 0.0f;
    #pragma unroll
    for (int e = 0; e < 8; e++) {
        rn[e] = d_n[base + e];
        rm[e] = m[base + e];
        sa[base + e] = rn[e];
        racc[e] = 0.0f;
    }
    __syncthreads();

    // one RK4 stage: rk[] = T(sa)
    #define STAGE()                                                              \
        _Pragma("unroll")                                                        \
        for (int e = 0; e < 8; e++) {                                            \
            const int i = base + e;                                              \
            const float ri = alphaT * rm[e] * sa[i];                             \
            float k;                                                             \
            if (i == 0) {                                                        \
                k = -ri * invDM;                                                 \
            } else {                                                             \
                const float mp = (e > 0) ? rm[e - 1] : rmL;                      \
                const float rim1 = alphaT * mp * sa[i - 1];                      \
                k = (i == MM - 1) ? (rim1 + ri) * invDM                          \
                                  : -(ri - rim1) * invDM;                        \
            }                                                                    \
            rk[e] = k;                                                           \
        }

    // k1
    STAGE();
    __syncthreads();
    #pragma unroll
    for (int e = 0; e < 8; e++) { racc[e] += rk[e]; sa[base + e] = rn[e] + h2 * rk[e]; }
    __syncthreads();
    // k2
    STAGE();
    __syncthreads();
    #pragma unroll
    for (int e = 0; e < 8; e++) { racc[e] += 2.0f * rk[e]; sa[base + e] = rn[e] + h2 * rk[e]; }
    __syncthreads();
    // k3
    STAGE();
    __syncthreads();
    #pragma unroll
    for (int e = 0; e < 8; e++) { racc[e] += 2.0f * rk[e]; sa[base + e] = rn[e] + h * rk[e]; }
    __syncthreads();
    // k4
    STAGE();
    #pragma unroll
    for (int e = 0; e < 8; e++) racc[e] += rk[e];
    #undef STAGE

    // n_tmp, G, v, uptake
    float upt = 0.0f;
    #pragma unroll
    for (int e = 0; e < 8; e++) {
        const int i = base + e;
        const float ntmp = rn[e] + h6 * racc[e];
        const float rg   = alphaE * rm[e];
        float gm = 1.0f / (1.0f - rm[e] + 1e-12f) - CGAM;
        if (gm < 0.0f) gm = 0.0f;
        const float G = gm * rg;
        d_ntmp[i] = ntmp;
        d_G[i]    = G;
        d_v[i]    = G * ntmp;
        upt += rg * ntmp;
    }
    sred[t] = upt;
    __syncthreads();
    for (int s = 512; s > 0; s >>= 1) {
        if (t < s) sred[t] += sred[t + s];
        __syncthreads();
    }
    if (t == 0) {
        const float uptake = sred[0] * DMF;
        const float Sn = Sh + h * (-0.1f * uptake);   // KAPPA = 0.1
        d_S = fmaxf(Sn, 0.0f);
    }
}

// ---------------- matvec partials: result[j] = sum_i v[i] * P[i,j] ----------------
// 256-bit loads; chunks < KEEP_CHUNKS use L2::evict_last (P constant across substeps
// -> steps 2..N hit L2 for this 88 MB slice), rest uses evict_first.
__global__ __launch_bounds__(128)
void k_matvec(const float* __restrict__ P, int step) {
    if (step >= d_N) return;
    __shared__ float sv[ROWS_PER_CHUNK];
    const int t  = threadIdx.x;                 // 0..127
    const int ct = blockIdx.x;                  // column tile (0..7)
    const int rc = blockIdx.y;                  // row chunk (0..63)
    const int r0 = rc * ROWS_PER_CHUNK;

    if (t < ROWS_PER_CHUNK) sv[t] = d_v[r0 + t];
    __syncthreads();

    const int j = ct * COLS_PER_TILE + t * 8;   // 8 floats per thread
    const char* Pr = (const char*)(P + (size_t)r0 * MM + j);
    float acc[8];
    #pragma unroll
    for (int e = 0; e < 8; e++) acc[e] = 0.0f;

    if (rc < KEEP_CHUNKS) {
        #pragma unroll 4
        for (int i = 0; i < ROWS_PER_CHUNK; i++) {
            const float vi = sv[i];
            const f8 p = ld_keep(Pr + (size_t)i * (MM * 4));
            #pragma unroll
            for (int e = 0; e < 8; e++) acc[e] += vi * p.v[e];
        }
    } else {
        #pragma unroll 4
        for (int i = 0; i < ROWS_PER_CHUNK; i++) {
            const float vi = sv[i];
            const f8 p = ld_stream(Pr + (size_t)i * (MM * 4));
            #pragma unroll
            for (int e = 0; e < 8; e++) acc[e] += vi * p.v[e];
        }
    }
    const int j4 = j >> 2;
    d_part4[(size_t)rc * (MM / 4) + j4]     = make_float4(acc[0], acc[1], acc[2], acc[3]);
    d_part4[(size_t)rc * (MM / 4) + j4 + 1] = make_float4(acc[4], acc[5], acc[6], acc[7]);
}

// ---------------- fast deterministic reduce + implicit reaction update ----------------
__global__ __launch_bounds__(128)
void k_update(int step) {
    if (step >= d_N) return;
    __shared__ float4 sp[128];
    const int t  = threadIdx.x;
    const int jl = t & 31;                       // local j4 index 0..31
    const int cg = t >> 5;                       // c-group 0..3
    const int j4 = blockIdx.x * 32 + jl;         // global float4 column

    float4 a = make_float4(0.f, 0.f, 0.f, 0.f);
    const int c0 = cg * (NROWCHUNK / 4);
    #pragma unroll
    for (int c = 0; c < NROWCHUNK / 4; c++) {
        const float4 p = d_part4[(size_t)(c0 + c) * (MM / 4) + j4];
        a.x += p.x; a.y += p.y; a.z += p.z; a.w += p.w;
    }
    sp[t] = a;
    __syncthreads();

    if (cg == 0) {
        const float4 b1 = sp[32 + jl];
        const float4 b2 = sp[64 + jl];
        const float4 b3 = sp[96 + jl];
        a = sp[jl];
        a.x += b1.x; a.y += b1.y; a.z += b1.z; a.w += b1.w;
        a.x += b2.x; a.y += b2.y; a.z += b2.z; a.w += b2.w;
        a.x += b3.x; a.y += b3.y; a.z += b3.z; a.w += b3.w;

        const float h = d_h;
        const float4 nt = ((const float4*)d_ntmp)[j4];
        const float4 Gg = ((const float4*)d_G)[j4];
        float4 nn;
        nn.x = fmaxf((nt.x + h * (COEF2DM * a.x)) / (1.0f + h * Gg.x), 0.0f);
        nn.y = fmaxf((nt.y + h * (COEF2DM * a.y)) / (1.0f + h * Gg.y), 0.0f);
        nn.z = fmaxf((nt.z + h * (COEF2DM * a.z)) / (1.0f + h * Gg.z), 0.0f);
        nn.w = fmaxf((nt.w + h * (COEF2DM * a.w)) / (1.0f + h * Gg.w), 0.0f);
        ((float4*)d_n)[j4] = nn;
    }
}

// ---------------- output ----------------
__global__ void k_final(float* __restrict__ out) {
    const int j = blockIdx.x * blockDim.x + threadIdx.x;
    if (j < MM) out[j] = d_n[j];
    if (j == 0) out[MM] = d_S;
}

extern "C" void kernel_launch(void* const* d_in, const int* in_sizes, int n_in,
                              void* d_out, int out_size) {
    const float* x = nullptr;
    const float* m = nullptr;
    const float* P = nullptr;
    for (int i = 0; i < n_in; i++) {
        if (in_sizes[i] == MM + 1)       x = (const float*)d_in[i];
        else if (in_sizes[i] == MM)      m = (const float*)d_in[i];
        else if (in_sizes[i] == MM * MM) P = (const float*)d_in[i];
    }
    float* out = (float*)d_out;

    k_init<<<1, 256>>>(x, m);
    for (int s = 0; s < KMAX; s++) {
        k_transport<<<1, 1024>>>(m, s);
        k_matvec<<<dim3(NCOLTILE, NROWCHUNK), 128>>>(P, s);
        k_update<<<MM / 128, 128>>>(s);
    }
    k_final<<<(MM + 128) / 128, 128>>>(out);
}